// round 11
// baseline (speedup 1.0000x reference)
#include <cuda_runtime.h>
#include <cuda_bf16.h>
#include <cstdint>

// phi = exp(-sum_d |x[i,d]-g[j,d]|/ls[d]) @ chol_inv (lower-tri), [4096,4096] fp32.
// R10 engine: int8 IMMA (m16n8k32) fixed-point 2-plane split, exact-A epilogue add.
//   C = A@(chol-I) [int8 planes, dynamic scales] + A [fp32 exact]
//   A: per-row scale 126/rowmax; B: global scale 126/max|chol-I|.
//   S = S11 + (S10+S01)/254  (S00 dropped, ~2^-16 level)

#define N_PTS 4096
#define M_PTS 4096
#define DIMS 8
#define NTILES 2048                        // 32 row-blocks x 64 col-blocks (128x64)
#define NWORKERS 296

__device__ char  g_A1[(size_t)N_PTS * M_PTS];
__device__ char  g_A0[(size_t)N_PTS * M_PTS];
__device__ char  g_B1[(size_t)M_PTS * M_PTS];   // T^T: [j][k]
__device__ char  g_B0[(size_t)M_PTS * M_PTS];
__device__ float g_Afull[(size_t)N_PTS * M_PTS];
__device__ float g_rmax[N_PTS];
__device__ int   g_bmaxbits;
__device__ unsigned int g_ticket;

__device__ __forceinline__ uint32_t smem_u32(const void* p) {
    uint32_t a;
    asm("{ .reg .u64 t; cvta.to.shared.u64 t, %1; cvt.u32.u64 %0, t; }" : "=r"(a) : "l"(p));
    return a;
}

__global__ void reset_state() { g_ticket = 0; g_bmaxbits = 0; }

// ---------------------------------------------------------------------------
// Stage 1: k_star row -> fp32 (g_Afull) + int8 planes with per-row scale
// ---------------------------------------------------------------------------
__global__ __launch_bounds__(256) void kstar_quant(
    const float* __restrict__ x, const float* __restrict__ grid,
    const float* __restrict__ ls)
{
    __shared__ float e[M_PTS];
    __shared__ float wred[8];
    __shared__ float xs[DIMS], rls[DIMS];

    const int i = blockIdx.x;
    const int tid = threadIdx.x;
    const int lane = tid & 31, wid = tid >> 5;

    if (tid < DIMS) {
        xs[tid]  = x[(size_t)i * DIMS + tid];
        rls[tid] = 1.442695040888963f / ls[tid];
    }
    __syncthreads();
    float xr[DIMS], rl[DIMS];
#pragma unroll
    for (int d = 0; d < DIMS; d++) { xr[d] = xs[d]; rl[d] = rls[d]; }

    const float4* g4 = reinterpret_cast<const float4*>(grid);
    float lmax = 0.0f;
    for (int j = tid; j < M_PTS; j += 256) {
        float4 a = g4[2 * j];
        float4 b = g4[2 * j + 1];
        float s = fabsf(xr[0] - a.x) * rl[0] + fabsf(xr[1] - a.y) * rl[1]
                + fabsf(xr[2] - a.z) * rl[2] + fabsf(xr[3] - a.w) * rl[3]
                + fabsf(xr[4] - b.x) * rl[4] + fabsf(xr[5] - b.y) * rl[5]
                + fabsf(xr[6] - b.z) * rl[6] + fabsf(xr[7] - b.w) * rl[7];
        float ev = exp2f(-s);
        e[j] = ev;
        lmax = fmaxf(lmax, ev);
    }
#pragma unroll
    for (int o = 16; o; o >>= 1) lmax = fmaxf(lmax, __shfl_xor_sync(~0u, lmax, o));
    if (lane == 0) wred[wid] = lmax;
    __syncthreads();
    if (tid == 0) {
        float m = wred[0];
#pragma unroll
        for (int w = 1; w < 8; w++) m = fmaxf(m, wred[w]);
        wred[0] = m;
        g_rmax[i] = m;
    }
    __syncthreads();
    const float sA = 126.0f / wred[0];

    char* a1p = g_A1 + (size_t)i * M_PTS;
    char* a0p = g_A0 + (size_t)i * M_PTS;
    float* afp = g_Afull + (size_t)i * M_PTS;
    for (int j4 = tid * 4; j4 < M_PTS; j4 += 1024) {
        float4 ev = *reinterpret_cast<float4*>(&e[j4]);
        float vv[4] = {ev.x, ev.y, ev.z, ev.w};
        char q1[4], q0[4];
#pragma unroll
        for (int q = 0; q < 4; q++) {
            float v = vv[q] * sA;
            int i1 = __float2int_rn(v);
            int i0 = __float2int_rn((v - (float)i1) * 254.0f);
            q1[q] = (char)i1;
            q0[q] = (char)i0;
        }
        *reinterpret_cast<char4*>(a1p + j4) = make_char4(q1[0], q1[1], q1[2], q1[3]);
        *reinterpret_cast<char4*>(a0p + j4) = make_char4(q0[0], q0[1], q0[2], q0[3]);
        *reinterpret_cast<float4*>(afp + j4) = ev;
    }
}

// ---------------------------------------------------------------------------
// Stage 2a: global max|chol - I|
// ---------------------------------------------------------------------------
__global__ __launch_bounds__(256) void bmax_kernel(const float* __restrict__ chol)
{
    __shared__ float wred[8];
    const size_t base = (size_t)blockIdx.x * M_PTS;
    const int tid = threadIdx.x, lane = tid & 31, wid = tid >> 5;
    float lmax = 0.0f;
    for (int t = tid; t < M_PTS; t += 256) {
        size_t idx = base + t;
        int k = (int)(idx >> 12), j = (int)(idx & 4095);
        float v = chol[idx] - (k == j ? 1.0f : 0.0f);
        lmax = fmaxf(lmax, fabsf(v));
    }
#pragma unroll
    for (int o = 16; o; o >>= 1) lmax = fmaxf(lmax, __shfl_xor_sync(~0u, lmax, o));
    if (lane == 0) wred[wid] = lmax;
    __syncthreads();
    if (tid == 0) {
        float m = wred[0];
#pragma unroll
        for (int w = 1; w < 8; w++) m = fmaxf(m, wred[w]);
        atomicMax(&g_bmaxbits, __float_as_int(m));
    }
}

// ---------------------------------------------------------------------------
// Stage 2b: transpose chol-I -> [j][k] int8 planes, global scale
// ---------------------------------------------------------------------------
__global__ __launch_bounds__(256) void transpose_quant(const float* __restrict__ chol)
{
    __shared__ float t[32][33];
    const int tx = threadIdx.x, ty = threadIdx.y;   // (32, 8)
    const int j0 = blockIdx.x * 32, k0 = blockIdx.y * 32;
#pragma unroll
    for (int r = 0; r < 32; r += 8)
        t[ty + r][tx] = chol[(size_t)(k0 + ty + r) * M_PTS + j0 + tx];
    __syncthreads();

    const float sB = 126.0f / __int_as_float(g_bmaxbits);
    const int tid = ty * 32 + tx;
    const int jj = tid >> 3;          // 0..31
    const int kg = tid & 7;           // 0..7
    char q1[4], q0[4];
#pragma unroll
    for (int q = 0; q < 4; q++) {
        int kk = kg * 4 + q;
        float v = t[kk][jj] - ((k0 + kk) == (j0 + jj) ? 1.0f : 0.0f);
        float vs = v * sB;
        int i1 = __float2int_rn(vs);
        int i0 = __float2int_rn((vs - (float)i1) * 254.0f);
        q1[q] = (char)i1;
        q0[q] = (char)i0;
    }
    size_t o = (size_t)(j0 + jj) * M_PTS + k0 + kg * 4;
    *reinterpret_cast<char4*>(g_B1 + o) = make_char4(q1[0], q1[1], q1[2], q1[3]);
    *reinterpret_cast<char4*>(g_B0 + o) = make_char4(q0[0], q0[1], q0[2], q0[3]);
}

// ---------------------------------------------------------------------------
// Stage 3: persistent IMMA GEMM. CTA tile 128x64, BK=64, 4 warps (64x32 each),
// smem rows 80B (16B-aligned phases, conflict-free ldmatrix), 2-stage, 2 CTA/SM.
// ---------------------------------------------------------------------------
#define BK 64
#define RSTRIDE 80
#define A_TILE (128 * RSTRIDE)                   // 10240
#define B_TILE (64 * RSTRIDE)                    // 5120
#define STAGE_B (2 * A_TILE + 2 * B_TILE)        // 30720
#define SMEM_B (2 * STAGE_B)                     // 61440

__device__ __forceinline__ void ldm4(uint32_t* r, uint32_t addr) {
    asm volatile("ldmatrix.sync.aligned.m8n8.x4.shared.b16 {%0,%1,%2,%3}, [%4];"
                 : "=r"(r[0]), "=r"(r[1]), "=r"(r[2]), "=r"(r[3]) : "r"(addr));
}
__device__ __forceinline__ void imma(int* c, const uint32_t* a, const uint32_t* b) {
    asm volatile(
        "mma.sync.aligned.m16n8k32.row.col.s32.s8.s8.s32 "
        "{%0,%1,%2,%3}, {%4,%5,%6,%7}, {%8,%9}, {%0,%1,%2,%3};"
        : "+r"(c[0]), "+r"(c[1]), "+r"(c[2]), "+r"(c[3])
        : "r"(a[0]), "r"(a[1]), "r"(a[2]), "r"(a[3]), "r"(b[0]), "r"(b[1]));
}
__device__ __forceinline__ void cpasync16(uint32_t saddr, const void* gaddr) {
    asm volatile("cp.async.cg.shared.global [%0], [%1], 16;" :: "r"(saddr), "l"(gaddr));
}

__device__ __forceinline__ void issue_chunk(uint32_t st, int row0, int col0, int k,
                                            int tid)
{
    const char* a1 = g_A1 + (size_t)row0 * M_PTS + k;
    const char* a0 = g_A0 + (size_t)row0 * M_PTS + k;
    const char* b1 = g_B1 + (size_t)col0 * M_PTS + k;
    const char* b0 = g_B0 + (size_t)col0 * M_PTS + k;
#pragma unroll
    for (int p = 0; p < 4; ++p) {               // A planes: 512 segs each
        int idx = p * 128 + tid;
        int row = idx >> 2, seg = idx & 3;
        uint32_t so = row * RSTRIDE + seg * 16;
        size_t go = (size_t)row * M_PTS + seg * 16;
        cpasync16(st + so, a1 + go);
        cpasync16(st + A_TILE + so, a0 + go);
    }
#pragma unroll
    for (int p = 0; p < 2; ++p) {               // B planes: 256 segs each
        int idx = p * 128 + tid;
        int row = idx >> 2, seg = idx & 3;
        uint32_t so = row * RSTRIDE + seg * 16;
        size_t go = (size_t)row * M_PTS + seg * 16;
        cpasync16(st + 2 * A_TILE + so, b1 + go);
        cpasync16(st + 2 * A_TILE + B_TILE + so, b0 + go);
    }
}

__global__ __launch_bounds__(128, 2) void gemm_imma(float* __restrict__ C)
{
    extern __shared__ char smem[];
    const uint32_t sb = smem_u32(smem);
    const int tid = threadIdx.x;
    const int lane = tid & 31, wid = tid >> 5;
    const int wm = wid >> 1;                  // 0..1: 64-row slab
    const int wn = wid & 1;                   // 0..1: 32-col slab

    const int lr = lane & 7, sel = lane >> 3;
    const int a_row = wm * 64 + lr + (sel & 1) * 8;
    const int a_koff = (sel >> 1) * 16;
    const int b_n = wn * 32 + (sel >> 1) * 8 + lr;
    const int b_koff = (sel & 1) * 16;

    const float bmaxT = __int_as_float(g_bmaxbits);
    __shared__ unsigned int s_tile;

    for (;;) {
        if (tid == 0) s_tile = atomicAdd(&g_ticket, 1u);
        __syncthreads();
        const unsigned int t = s_tile;
        __syncthreads();
        if (t >= NTILES) break;

        const int cb = (int)(t >> 5), rb = (int)(t & 31);  // cb asc = heaviest first
        const int row0 = rb * 128;
        const int col0 = cb * 64;
        const int k0 = col0;
        const int nchunk = (M_PTS - k0) / BK;   // 64 - cb >= 1

        int acc1[4][4][4], acc2[4][4][4];
#pragma unroll
        for (int i = 0; i < 4; ++i)
#pragma unroll
            for (int j = 0; j < 4; ++j)
#pragma unroll
                for (int q = 0; q < 4; ++q) { acc1[i][j][q] = 0; acc2[i][j][q] = 0; }

        issue_chunk(sb, row0, col0, k0, tid);
        asm volatile("cp.async.commit_group;");
        if (nchunk > 1) issue_chunk(sb + STAGE_B, row0, col0, k0 + BK, tid);
        asm volatile("cp.async.commit_group;");

        for (int c = 0; c < nchunk; ++c) {
            asm volatile("cp.async.wait_group 1;");
            __syncthreads();
            const uint32_t st = sb + (c & 1) * STAGE_B;
            const uint32_t A1s = st, A0s = st + A_TILE;
            const uint32_t B1s = st + 2 * A_TILE, B0s = B1s + B_TILE;

#pragma unroll
            for (int ks = 0; ks < 2; ++ks) {
                const int kb = ks * 32;
                uint32_t a1f[4][4], a0f[4][4], b1f[2][4], b0f[2][4];
#pragma unroll
                for (int i = 0; i < 4; ++i) {
                    uint32_t off = (a_row + i * 16) * RSTRIDE + kb + a_koff;
                    ldm4(a1f[i], A1s + off);
                    ldm4(a0f[i], A0s + off);
                }
#pragma unroll
                for (int g = 0; g < 2; ++g) {
                    uint32_t off = (b_n + g * 16) * RSTRIDE + kb + b_koff;
                    ldm4(b1f[g], B1s + off);
                    ldm4(b0f[g], B0s + off);
                }
#pragma unroll
                for (int i = 0; i < 4; ++i)
#pragma unroll
                    for (int j = 0; j < 4; ++j) {
                        const uint32_t* p1 = &b1f[j >> 1][(j & 1) * 2];
                        const uint32_t* p0 = &b0f[j >> 1][(j & 1) * 2];
                        imma(acc1[i][j], a1f[i], p1);
                        imma(acc2[i][j], a1f[i], p0);
                        imma(acc2[i][j], a0f[i], p1);
                    }
            }
            __syncthreads();
            if (c + 2 < nchunk)
                issue_chunk(st, row0, col0, k0 + (c + 2) * BK, tid);
            asm volatile("cp.async.commit_group;");
        }

        asm volatile("cp.async.wait_group 0;");
        __syncthreads();

        // Epilogue: C = (S11 + S2/254) * rowmax*bmax/126^2 + A_exact
        const int er = lane >> 2;
        const int ec = (lane & 3) * 2;
        const float kconst = bmaxT * (1.0f / (126.0f * 126.0f));
#pragma unroll
        for (int i = 0; i < 4; ++i) {
            const int r_lo = row0 + wm * 64 + i * 16 + er;
            const int r_hi = r_lo + 8;
            const float sc_lo = g_rmax[r_lo] * kconst;
            const float sc_hi = g_rmax[r_hi] * kconst;
#pragma unroll
            for (int j = 0; j < 4; ++j) {
                const int cc = col0 + wn * 32 + j * 8 + ec;
                float2 alo = *reinterpret_cast<const float2*>(
                    g_Afull + (size_t)r_lo * M_PTS + cc);
                float2 ahi = *reinterpret_cast<const float2*>(
                    g_Afull + (size_t)r_hi * M_PTS + cc);
                float2 vlo, vhi;
                vlo.x = ((float)acc1[i][j][0] + (float)acc2[i][j][0] * (1.0f/254.0f)) * sc_lo + alo.x;
                vlo.y = ((float)acc1[i][j][1] + (float)acc2[i][j][1] * (1.0f/254.0f)) * sc_lo + alo.y;
                vhi.x = ((float)acc1[i][j][2] + (float)acc2[i][j][2] * (1.0f/254.0f)) * sc_hi + ahi.x;
                vhi.y = ((float)acc1[i][j][3] + (float)acc2[i][j][3] * (1.0f/254.0f)) * sc_hi + ahi.y;
                *reinterpret_cast<float2*>(C + (size_t)r_lo * M_PTS + cc) = vlo;
                *reinterpret_cast<float2*>(C + (size_t)r_hi * M_PTS + cc) = vhi;
            }
        }
    }
}

// ---------------------------------------------------------------------------
extern "C" void kernel_launch(void* const* d_in, const int* in_sizes, int n_in,
                              void* d_out, int out_size)
{
    const float* x    = (const float*)d_in[0];
    const float* grid = (const float*)d_in[1];
    const float* chol = (const float*)d_in[2];
    const float* ls   = (const float*)d_in[3];
    float* out = (float*)d_out;

    cudaFuncSetAttribute(gemm_imma, cudaFuncAttributeMaxDynamicSharedMemorySize, SMEM_B);

    reset_state<<<1, 1>>>();
    kstar_quant<<<N_PTS, 256>>>(x, grid, ls);
    bmax_kernel<<<4096, 256>>>(chol);
    transpose_quant<<<dim3(M_PTS / 32, M_PTS / 32), dim3(32, 8)>>>(chol);
    gemm_imma<<<NWORKERS, 128, SMEM_B>>>(out);
}

// round 14
// speedup vs baseline: 2.3855x; 2.3855x over previous
#include <cuda_runtime.h>
#include <cuda_fp16.h>
#include <cstdint>

// phi = exp(-sum_d |x[i,d]-g[j,d]|/ls[d]) @ chol_inv (lower-tri), [4096,4096] fp32.
// R12 engine: fp16 HMMA 2-product split: C = Ah*Bh + Ah*Bl,
//   Ah = fp16(k_star); Bh = fp16(T), Bl = fp16(T - Bh) (T = chol_inv^T tiles).
// Persistent CTAs + atomic ticket (heaviest-first), 128x128 tile, BK=32,
// 4 warps (64x64), 3-stage cp.async, 2 CTA/SM.

#define N_PTS 4096
#define M_PTS 4096
#define DIMS 8
#define NTILES 1024
#define NWORKERS 296

__device__ __half g_Ah[(size_t)N_PTS * M_PTS];
__device__ __half g_Bh[(size_t)M_PTS * M_PTS];   // T^T: [j][k]
__device__ __half g_Bl[(size_t)M_PTS * M_PTS];
__device__ unsigned int g_ticket;

__device__ __forceinline__ uint32_t smem_u32(const void* p) {
    uint32_t a;
    asm("{ .reg .u64 t; cvta.to.shared.u64 t, %1; cvt.u32.u64 %0, t; }" : "=r"(a) : "l"(p));
    return a;
}

__global__ void reset_ticket() { g_ticket = 0; }

// ---------------------------------------------------------------------------
// Stage 1: k_star -> fp16 (single plane)
// ---------------------------------------------------------------------------
__global__ __launch_bounds__(256) void kstar_half(
    const float* __restrict__ x, const float* __restrict__ grid,
    const float* __restrict__ ls)
{
    const int i = blockIdx.x;
    __shared__ float xs[DIMS], rls[DIMS];
    if (threadIdx.x < DIMS) {
        xs[threadIdx.x]  = x[(size_t)i * DIMS + threadIdx.x];
        rls[threadIdx.x] = 1.442695040888963f / ls[threadIdx.x];
    }
    __syncthreads();
    float xr[DIMS], rl[DIMS];
#pragma unroll
    for (int d = 0; d < DIMS; d++) { xr[d] = xs[d]; rl[d] = rls[d]; }

    const float4* g4 = reinterpret_cast<const float4*>(grid);
    __half* oh = g_Ah + (size_t)i * M_PTS;

    for (int j = threadIdx.x; j < M_PTS; j += blockDim.x) {
        float4 a = g4[2 * j];
        float4 b = g4[2 * j + 1];
        float s = fabsf(xr[0] - a.x) * rl[0] + fabsf(xr[1] - a.y) * rl[1]
                + fabsf(xr[2] - a.z) * rl[2] + fabsf(xr[3] - a.w) * rl[3]
                + fabsf(xr[4] - b.x) * rl[4] + fabsf(xr[5] - b.y) * rl[5]
                + fabsf(xr[6] - b.z) * rl[6] + fabsf(xr[7] - b.w) * rl[7];
        oh[j] = __float2half_rn(exp2f(-s));
    }
}

// ---------------------------------------------------------------------------
// Stage 2: transpose chol -> [j][k] fp16 hi/lo planes
// ---------------------------------------------------------------------------
__global__ __launch_bounds__(256) void transpose_half(const float* __restrict__ chol)
{
    __shared__ float t[32][33];
    const int tx = threadIdx.x, ty = threadIdx.y;   // (32, 8)
    const int j0 = blockIdx.x * 32, k0 = blockIdx.y * 32;
#pragma unroll
    for (int r = 0; r < 32; r += 8)
        t[ty + r][tx] = chol[(size_t)(k0 + ty + r) * M_PTS + j0 + tx];
    __syncthreads();
#pragma unroll
    for (int r = 0; r < 32; r += 8) {
        float v = t[tx][ty + r];
        __half h = __float2half_rn(v);
        float rem = v - __half2float(h);
        size_t o = (size_t)(j0 + ty + r) * M_PTS + k0 + tx;
        g_Bh[o] = h;
        g_Bl[o] = __float2half_rn(rem);
    }
}

// ---------------------------------------------------------------------------
// Stage 3: persistent HMMA GEMM, fp16 2-product split, 3-stage cp.async.
// ---------------------------------------------------------------------------
#define BK 32
#define KSTRIDE 40
#define TILE_B (128 * KSTRIDE * 2)              // 10240 bytes
#define STAGE_B (3 * TILE_B)                    // Ah, Bh, Bl = 30720
#define NSTAGE 3
#define SMEM_B (NSTAGE * STAGE_B)               // 92160

__device__ __forceinline__ void ldm4(uint32_t* r, uint32_t addr) {
    asm volatile("ldmatrix.sync.aligned.m8n8.x4.shared.b16 {%0,%1,%2,%3}, [%4];"
                 : "=r"(r[0]), "=r"(r[1]), "=r"(r[2]), "=r"(r[3]) : "r"(addr));
}
__device__ __forceinline__ void mma_f16(float* c, const uint32_t* a, const uint32_t* b) {
    asm volatile(
        "mma.sync.aligned.m16n8k16.row.col.f32.f16.f16.f32 "
        "{%0,%1,%2,%3}, {%4,%5,%6,%7}, {%8,%9}, {%0,%1,%2,%3};"
        : "+f"(c[0]), "+f"(c[1]), "+f"(c[2]), "+f"(c[3])
        : "r"(a[0]), "r"(a[1]), "r"(a[2]), "r"(a[3]), "r"(b[0]), "r"(b[1]));
}
__device__ __forceinline__ void cpasync16(uint32_t saddr, const void* gaddr) {
    asm volatile("cp.async.cg.shared.global [%0], [%1], 16;" :: "r"(saddr), "l"(gaddr));
}

__device__ __forceinline__ void issue_chunk(uint32_t st, int row0, int col0, int k,
                                            int tid)
{
    const __half* srcs[3] = {
        g_Ah + (size_t)row0 * M_PTS,
        g_Bh + (size_t)col0 * M_PTS,
        g_Bl + (size_t)col0 * M_PTS };
#pragma unroll
    for (int t = 0; t < 3; ++t) {
        uint32_t sb = st + t * TILE_B;
        const __half* src = srcs[t];
#pragma unroll
        for (int p = 0; p < 4; ++p) {          // 512 x 16B per tile / 128 thr
            int idx = p * 128 + tid;
            int row = idx >> 2;
            int seg = idx & 3;
            cpasync16(sb + row * (KSTRIDE * 2) + seg * 16,
                      src + (size_t)row * M_PTS + k + seg * 8);
        }
    }
}

__global__ __launch_bounds__(128, 2) void gemm_hmma(float* __restrict__ C)
{
    extern __shared__ char smem[];
    const uint32_t sb = smem_u32(smem);
    const int tid = threadIdx.x;
    const int lane = tid & 31, wid = tid >> 5;
    const int wm = wid >> 1;                  // 0..1 (64-row slabs)
    const int wn = wid & 1;                   // 0..1 (64-col slabs)

    const int lr = lane & 7, sel = lane >> 3;
    const int a_row_base = wm * 64 + lr + (sel & 1) * 8;
    const int a_col_base = (sel >> 1) * 8;
    const int b_row_base = wn * 64 + (sel >> 1) * 8 + lr;
    const int b_col_base = (sel & 1) * 8;

    __shared__ unsigned int s_tile;

    for (;;) {
        if (tid == 0) s_tile = atomicAdd(&g_ticket, 1u);
        __syncthreads();
        const unsigned int t = s_tile;
        __syncthreads();
        if (t >= NTILES) break;

        // cb ascending == heaviest first (k0 = col0 triangular skip)
        const int cb = (int)(t >> 5), rb = (int)(t & 31);
        const int row0 = rb * 128;
        const int col0 = cb * 128;
        const int k0 = col0;
        const int nchunk = (M_PTS - k0) / BK;

        float acc[4][8][4];
#pragma unroll
        for (int i = 0; i < 4; ++i)
#pragma unroll
            for (int j = 0; j < 8; ++j)
#pragma unroll
                for (int q = 0; q < 4; ++q) acc[i][j][q] = 0.0f;

#pragma unroll
        for (int s = 0; s < NSTAGE; ++s) {
            if (s < nchunk) issue_chunk(sb + s * STAGE_B, row0, col0, k0 + s * BK, tid);
            asm volatile("cp.async.commit_group;");
        }

        int stg = 0;
        for (int c = 0; c < nchunk; ++c) {
            asm volatile("cp.async.wait_group %0;" :: "n"(NSTAGE - 1));
            __syncthreads();
            const uint32_t st = sb + stg * STAGE_B;
            const uint32_t Ah = st, Bh = st + TILE_B, Bl = st + 2 * TILE_B;

#pragma unroll
            for (int ks = 0; ks < 2; ++ks) {
                const int kel = ks * 16;
                uint32_t ah[4][4], bh[4][4], bl[4][4];
#pragma unroll
                for (int i = 0; i < 4; ++i) {
                    uint32_t off = (a_row_base + i * 16) * (KSTRIDE * 2)
                                 + (kel + a_col_base) * 2;
                    ldm4(ah[i], Ah + off);
                }
#pragma unroll
                for (int jp = 0; jp < 4; ++jp) {
                    uint32_t off = (b_row_base + jp * 16) * (KSTRIDE * 2)
                                 + (kel + b_col_base) * 2;
                    ldm4(bh[jp], Bh + off);
                    ldm4(bl[jp], Bl + off);
                }
#pragma unroll
                for (int i = 0; i < 4; ++i)
#pragma unroll
                    for (int j = 0; j < 8; ++j) {
                        const uint32_t* bhj = &bh[j >> 1][(j & 1) * 2];
                        const uint32_t* blj = &bl[j >> 1][(j & 1) * 2];
                        mma_f16(acc[i][j], ah[i], bhj);
                        mma_f16(acc[i][j], ah[i], blj);
                    }
            }
            __syncthreads();
            if (c + NSTAGE < nchunk)
                issue_chunk(sb + stg * STAGE_B, row0, col0, k0 + (c + NSTAGE) * BK, tid);
            asm volatile("cp.async.commit_group;");
            stg = (stg + 1 == NSTAGE) ? 0 : stg + 1;
        }

        asm volatile("cp.async.wait_group 0;");
        __syncthreads();

        // Epilogue
        const int er = lane >> 2;
        const int ec = (lane & 3) * 2;
#pragma unroll
        for (int i = 0; i < 4; ++i) {
#pragma unroll
            for (int j = 0; j < 8; ++j) {
                int r = row0 + wm * 64 + i * 16 + er;
                int cc = col0 + wn * 64 + j * 8 + ec;
                *reinterpret_cast<float2*>(C + (size_t)r * M_PTS + cc)
                    = make_float2(acc[i][j][0], acc[i][j][1]);
                *reinterpret_cast<float2*>(C + (size_t)(r + 8) * M_PTS + cc)
                    = make_float2(acc[i][j][2], acc[i][j][3]);
            }
        }
    }
}

// ---------------------------------------------------------------------------
extern "C" void kernel_launch(void* const* d_in, const int* in_sizes, int n_in,
                              void* d_out, int out_size)
{
    const float* x    = (const float*)d_in[0];
    const float* grid = (const float*)d_in[1];
    const float* chol = (const float*)d_in[2];
    const float* ls   = (const float*)d_in[3];
    float* out = (float*)d_out;

    cudaFuncSetAttribute(gemm_hmma, cudaFuncAttributeMaxDynamicSharedMemorySize, SMEM_B);

    reset_ticket<<<1, 1>>>();
    kstar_half<<<N_PTS, 256>>>(x, grid, ls);
    transpose_half<<<dim3(M_PTS / 32, M_PTS / 32), dim3(32, 8)>>>(chol);
    gemm_hmma<<<NWORKERS, 128, SMEM_B>>>(out);
}

// round 17
// speedup vs baseline: 2.9835x; 1.2507x over previous
#include <cuda_runtime.h>
#include <cuda_bf16.h>
#include <cstdint>

// phi = exp(-sum_d |x[i,d]-g[j,d]|/ls[d]) @ chol_inv (lower-tri), [4096,4096] fp32.
// Engine: bf16 HMMA hi/lo split x3 (proven fastest legacy format on sm_103a).
// R15: 3-stage cp.async ring, ONE barrier per chunk, BK=16 (KSTRIDE=24, 48B rows),
// persistent ticket heaviest-first, 128x128 tile, 4 warps (64x64), 2 CTA/SM.

#define N_PTS 4096
#define M_PTS 4096
#define DIMS 8
#define NTILES 1024
#define NWORKERS 296

__device__ __nv_bfloat16 g_Ah[(size_t)N_PTS * M_PTS];
__device__ __nv_bfloat16 g_Al[(size_t)N_PTS * M_PTS];
__device__ __nv_bfloat16 g_Bh[(size_t)M_PTS * M_PTS];   // T^T: [j][k]
__device__ __nv_bfloat16 g_Bl[(size_t)M_PTS * M_PTS];
__device__ unsigned int g_ticket;

__device__ __forceinline__ uint32_t smem_u32(const void* p) {
    uint32_t a;
    asm("{ .reg .u64 t; cvta.to.shared.u64 t, %1; cvt.u32.u64 %0, t; }" : "=r"(a) : "l"(p));
    return a;
}

__global__ void reset_ticket() { g_ticket = 0; }

// ---------------------------------------------------------------------------
// Stage 1: k_star -> bf16 hi/lo
// ---------------------------------------------------------------------------
__global__ __launch_bounds__(256) void kstar_split(
    const float* __restrict__ x, const float* __restrict__ grid,
    const float* __restrict__ ls)
{
    const int i = blockIdx.x;
    __shared__ float xs[DIMS], rls[DIMS];
    if (threadIdx.x < DIMS) {
        xs[threadIdx.x]  = x[(size_t)i * DIMS + threadIdx.x];
        rls[threadIdx.x] = 1.442695040888963f / ls[threadIdx.x];
    }
    __syncthreads();
    float xr[DIMS], rl[DIMS];
#pragma unroll
    for (int d = 0; d < DIMS; d++) { xr[d] = xs[d]; rl[d] = rls[d]; }

    const float4* g4 = reinterpret_cast<const float4*>(grid);
    __nv_bfloat16* oh = g_Ah + (size_t)i * M_PTS;
    __nv_bfloat16* ol = g_Al + (size_t)i * M_PTS;

    for (int j = threadIdx.x; j < M_PTS; j += blockDim.x) {
        float4 a = g4[2 * j];
        float4 b = g4[2 * j + 1];
        float s = fabsf(xr[0] - a.x) * rl[0] + fabsf(xr[1] - a.y) * rl[1]
                + fabsf(xr[2] - a.z) * rl[2] + fabsf(xr[3] - a.w) * rl[3]
                + fabsf(xr[4] - b.x) * rl[4] + fabsf(xr[5] - b.y) * rl[5]
                + fabsf(xr[6] - b.z) * rl[6] + fabsf(xr[7] - b.w) * rl[7];
        float e = exp2f(-s);
        __nv_bfloat16 h = __float2bfloat16(e);
        float rem = e - __bfloat162float(h);
        oh[j] = h;
        ol[j] = __float2bfloat16(rem);
    }
}

// ---------------------------------------------------------------------------
// Stage 2: transpose chol -> [j][k] bf16 hi/lo
// ---------------------------------------------------------------------------
__global__ __launch_bounds__(256) void transpose_split(const float* __restrict__ chol)
{
    __shared__ float t[32][33];
    const int tx = threadIdx.x, ty = threadIdx.y;   // (32, 8)
    const int j0 = blockIdx.x * 32, k0 = blockIdx.y * 32;
#pragma unroll
    for (int r = 0; r < 32; r += 8)
        t[ty + r][tx] = chol[(size_t)(k0 + ty + r) * M_PTS + j0 + tx];
    __syncthreads();
#pragma unroll
    for (int r = 0; r < 32; r += 8) {
        float v = t[tx][ty + r];
        __nv_bfloat16 h = __float2bfloat16(v);
        float rem = v - __bfloat162float(h);
        size_t o = (size_t)(j0 + ty + r) * M_PTS + k0 + tx;
        g_Bh[o] = h;
        g_Bl[o] = __float2bfloat16(rem);
    }
}

// ---------------------------------------------------------------------------
// Stage 3: persistent HMMA GEMM, bf16 x3, BK=16, 3-stage ring, 1 barrier/chunk.
// ---------------------------------------------------------------------------
#define BK 16
#define KSTRIDE 24                               // elems; 48B rows, conflict-free
#define TILE_B (128 * KSTRIDE * 2)               // 6144
#define STAGE_B (4 * TILE_B)                     // Ah, Al, Bh, Bl = 24576
#define NSTAGE 3
#define SMEM_B (NSTAGE * STAGE_B)                // 73728

__device__ __forceinline__ void ldm4(uint32_t* r, uint32_t addr) {
    asm volatile("ldmatrix.sync.aligned.m8n8.x4.shared.b16 {%0,%1,%2,%3}, [%4];"
                 : "=r"(r[0]), "=r"(r[1]), "=r"(r[2]), "=r"(r[3]) : "r"(addr));
}
__device__ __forceinline__ void mma_bf16(float* c, const uint32_t* a, const uint32_t* b) {
    asm volatile(
        "mma.sync.aligned.m16n8k16.row.col.f32.bf16.bf16.f32 "
        "{%0,%1,%2,%3}, {%4,%5,%6,%7}, {%8,%9}, {%0,%1,%2,%3};"
        : "+f"(c[0]), "+f"(c[1]), "+f"(c[2]), "+f"(c[3])
        : "r"(a[0]), "r"(a[1]), "r"(a[2]), "r"(a[3]), "r"(b[0]), "r"(b[1]));
}
__device__ __forceinline__ void cpasync16(uint32_t saddr, const void* gaddr) {
    asm volatile("cp.async.cg.shared.global [%0], [%1], 16;" :: "r"(saddr), "l"(gaddr));
}

// One chunk = 4 planes x 128 rows x 32B (2 segs) = 1024 segs; 8 per thread.
__device__ __forceinline__ void issue_chunk(uint32_t st, int row0, int col0, int k,
                                            int tid)
{
    const __nv_bfloat16* srcs[4] = {
        g_Ah + (size_t)row0 * M_PTS, g_Al + (size_t)row0 * M_PTS,
        g_Bh + (size_t)col0 * M_PTS, g_Bl + (size_t)col0 * M_PTS };
#pragma unroll
    for (int t = 0; t < 4; ++t) {
        uint32_t sbuf = st + t * TILE_B;
        const __nv_bfloat16* src = srcs[t];
#pragma unroll
        for (int p = 0; p < 2; ++p) {
            int idx = p * 128 + tid;            // 256 segs per plane
            int row = idx >> 1;
            int seg = idx & 1;
            cpasync16(sbuf + row * (KSTRIDE * 2) + seg * 16,
                      src + (size_t)row * M_PTS + k + seg * 8);
        }
    }
}

__global__ __launch_bounds__(128, 2) void gemm_hmma(float* __restrict__ C)
{
    extern __shared__ char smem[];
    const uint32_t sb = smem_u32(smem);
    const int tid = threadIdx.x;
    const int lane = tid & 31, wid = tid >> 5;
    const int wm = wid >> 1;                  // 0..1 (64-row slabs)
    const int wn = wid & 1;                   // 0..1 (64-col slabs)

    const int lr = lane & 7, sel = lane >> 3;
    const int a_row_base = wm * 64 + lr + (sel & 1) * 8;
    const int a_col_off  = ((sel >> 1) * 8) * 2;     // bytes: 0 or 16
    const int b_row_base = wn * 64 + (sel >> 1) * 8 + lr;
    const int b_col_off  = ((sel & 1) * 8) * 2;

    __shared__ unsigned int s_tile;

    for (;;) {
        if (tid == 0) s_tile = atomicAdd(&g_ticket, 1u);
        __syncthreads();
        const unsigned int t = s_tile;
        __syncthreads();
        if (t >= NTILES) break;

        // cb ascending == heaviest first (k0 = col0 triangular skip)
        const int cb = (int)(t >> 5), rb = (int)(t & 31);
        const int row0 = rb * 128;
        const int col0 = cb * 128;
        const int k0 = col0;
        const int nchunk = (M_PTS - k0) / BK;   // >= 8

        float acc[4][8][4];
#pragma unroll
        for (int i = 0; i < 4; ++i)
#pragma unroll
            for (int j = 0; j < 8; ++j)
#pragma unroll
                for (int q = 0; q < 4; ++q) acc[i][j][q] = 0.0f;

        // Prologue: stages 0,1
        issue_chunk(sb, row0, col0, k0, tid);
        asm volatile("cp.async.commit_group;");
        issue_chunk(sb + STAGE_B, row0, col0, k0 + BK, tid);
        asm volatile("cp.async.commit_group;");

        int stg = 0;                            // stage of chunk c
        int pstg = 2;                           // stage to fill with chunk c+2
        for (int c = 0; c < nchunk; ++c) {
            // chunk c's group complete (own copies), then all threads' copies
            asm volatile("cp.async.wait_group 1;");
            __syncthreads();

            const uint32_t st = sb + stg * STAGE_B;
            const uint32_t Ah = st, Al = st + TILE_B;
            const uint32_t Bh = st + 2 * TILE_B, Bl = st + 3 * TILE_B;

            // Load all fragments for this chunk (single k-step)
            uint32_t ah[4][4], al[4][4], bh[4][4], bl[4][4];
#pragma unroll
            for (int i = 0; i < 4; ++i) {
                uint32_t off = (a_row_base + i * 16) * (KSTRIDE * 2) + a_col_off;
                ldm4(ah[i], Ah + off);
                ldm4(al[i], Al + off);
            }
#pragma unroll
            for (int jp = 0; jp < 4; ++jp) {
                uint32_t off = (b_row_base + jp * 16) * (KSTRIDE * 2) + b_col_off;
                ldm4(bh[jp], Bh + off);
                ldm4(bl[jp], Bl + off);
            }

            // Prefetch chunk c+2 into the stage freed at iter c-1.
            // Safe: the barrier above guarantees all warps finished reading it.
            if (c + 2 < nchunk)
                issue_chunk(sb + pstg * STAGE_B, row0, col0, k0 + (c + 2) * BK, tid);
            asm volatile("cp.async.commit_group;");

            // MMAs (cp.asyncs above drain in this shadow)
#pragma unroll
            for (int i = 0; i < 4; ++i)
#pragma unroll
                for (int j = 0; j < 8; ++j) {
                    const uint32_t* bhj = &bh[j >> 1][(j & 1) * 2];
                    const uint32_t* blj = &bl[j >> 1][(j & 1) * 2];
                    mma_bf16(acc[i][j], ah[i], bhj);
                    mma_bf16(acc[i][j], ah[i], blj);
                    mma_bf16(acc[i][j], al[i], bhj);
                }

            stg = (stg + 1 == NSTAGE) ? 0 : stg + 1;
            pstg = (pstg + 1 == NSTAGE) ? 0 : pstg + 1;
        }

        asm volatile("cp.async.wait_group 0;");

        // Epilogue (no smem use; cross-tile smem safety via ticket barriers)
        const int er = lane >> 2;
        const int ec = (lane & 3) * 2;
#pragma unroll
        for (int i = 0; i < 4; ++i) {
#pragma unroll
            for (int j = 0; j < 8; ++j) {
                int r = row0 + wm * 64 + i * 16 + er;
                int cc = col0 + wn * 64 + j * 8 + ec;
                *reinterpret_cast<float2*>(C + (size_t)r * M_PTS + cc)
                    = make_float2(acc[i][j][0], acc[i][j][1]);
                *reinterpret_cast<float2*>(C + (size_t)(r + 8) * M_PTS + cc)
                    = make_float2(acc[i][j][2], acc[i][j][3]);
            }
        }
    }
}

// ---------------------------------------------------------------------------
extern "C" void kernel_launch(void* const* d_in, const int* in_sizes, int n_in,
                              void* d_out, int out_size)
{
    const float* x    = (const float*)d_in[0];
    const float* grid = (const float*)d_in[1];
    const float* chol = (const float*)d_in[2];
    const float* ls   = (const float*)d_in[3];
    float* out = (float*)d_out;

    cudaFuncSetAttribute(gemm_hmma, cudaFuncAttributeMaxDynamicSharedMemorySize, SMEM_B);

    reset_ticket<<<1, 1>>>();
    kstar_split<<<N_PTS, 256>>>(x, grid, ls);
    transpose_split<<<dim3(M_PTS / 32, M_PTS / 32), dim3(32, 8)>>>(chol);
    gemm_hmma<<<NWORKERS, 128, SMEM_B>>>(out);
}